// round 16
// baseline (speedup 1.0000x reference)
#include <cuda_runtime.h>

// Problem constants
#define NB    32
#define NBQ   8         // per-branch batch quarter
#define NBRANCH 4
#define C     4096
#define HW    784       // 28*28
#define HW4   196       // HW / 4 (float4 granularity)
#define NO    4         // output channels
#define CHUNKS 37       // 37*32 = 1184 k1 blocks total = 2 * (148 SMs * 4/SM)
#define CCMAX 111       // ceil(4096/37)

// Scratch (no allocation allowed)
__device__ float g_part[CHUNKS * NB * NO * HW];  // 14.86 MB partials (L2)
__device__ float g_cams[NB * NO * HW];           // 401 KB relu'd cams
__device__ float g_max[NB * NO];                 // per-(n,o) spatial max
__device__ float g_mean[NB * HW];                // 100 KB mean map

// ---------------------------------------------------------------------------
// Kernel 1: partial dot products for one batch quarter. grid=(CHUNKS, NBQ).
// x read with __ldcs (streaming); weights transposed in smem; unroll 8.
// ---------------------------------------------------------------------------
__global__ __launch_bounds__(256, 4) void k1_dot(const float* __restrict__ x,
                                                 const float* __restrict__ w,
                                                 int n_base) {
    const int cchunk = blockIdx.x;
    const int n      = n_base + blockIdx.y;
    const int tid    = threadIdx.x;

    const int cbeg = (cchunk * C) / CHUNKS;
    const int cend = ((cchunk + 1) * C) / CHUNKS;
    const int cc   = cend - cbeg;          // 110 or 111

    __shared__ float4 sw[CCMAX];           // transposed: sw[c] = {w0,w1,w2,w3}
    if (tid < cc) {
        int c = cbeg + tid;
        sw[tid] = make_float4(w[0 * C + c], w[1 * C + c],
                              w[2 * C + c], w[3 * C + c]);
    }
    __syncthreads();

    if (tid >= HW4) return;

    float a00 = 0.f, a01 = 0.f, a02 = 0.f, a03 = 0.f;
    float a10 = 0.f, a11 = 0.f, a12 = 0.f, a13 = 0.f;
    float a20 = 0.f, a21 = 0.f, a22 = 0.f, a23 = 0.f;
    float a30 = 0.f, a31 = 0.f, a32 = 0.f, a33 = 0.f;

    const float4* xb = (const float4*)(x + ((size_t)n * C + (size_t)cbeg) * HW) + tid;

#pragma unroll 8
    for (int c = 0; c < cc; c++) {
        float4 xv = __ldcs(xb + (size_t)c * HW4);
        float4 wv = sw[c];
        a00 += wv.x * xv.x; a01 += wv.x * xv.y; a02 += wv.x * xv.z; a03 += wv.x * xv.w;
        a10 += wv.y * xv.x; a11 += wv.y * xv.y; a12 += wv.y * xv.z; a13 += wv.y * xv.w;
        a20 += wv.z * xv.x; a21 += wv.z * xv.y; a22 += wv.z * xv.z; a23 += wv.z * xv.w;
        a30 += wv.w * xv.x; a31 += wv.w * xv.y; a32 += wv.w * xv.z; a33 += wv.w * xv.w;
    }

    const int hw = tid * 4;
    float* base = &g_part[(((size_t)cchunk * NB + n) * NO) * HW];
    *(float4*)(base + 0 * HW + hw) = make_float4(a00, a01, a02, a03);
    *(float4*)(base + 1 * HW + hw) = make_float4(a10, a11, a12, a13);
    *(float4*)(base + 2 * HW + hw) = make_float4(a20, a21, a22, a23);
    *(float4*)(base + 3 * HW + hw) = make_float4(a30, a31, a32, a33);
}

// ---------------------------------------------------------------------------
// Kernel 2a: chunk reduction + relu + per-(n,o) max for one quarter.
// grid = NBQ*NO = 32 blocks, 256 threads (power-of-2 tree).
// ---------------------------------------------------------------------------
__global__ __launch_bounds__(256) void k2a_reduce(int n_base) {
    const int no  = n_base * NO + blockIdx.x;
    const int n   = no >> 2;
    const int o   = no & 3;
    const int tid = threadIdx.x;

    float lmax = 0.f;                    // relu outputs >= 0
    if (tid < HW4) {
        const int hw = tid * 4;
        float sx = 0.f, sy = 0.f, sz = 0.f, sw_ = 0.f;
#pragma unroll
        for (int ch = 0; ch < CHUNKS; ch++) {
            const float* p = &g_part[(((size_t)ch * NB + n) * NO + o) * HW + hw];
            float4 cv = *(const float4*)p;
            sx += cv.x; sy += cv.y; sz += cv.z; sw_ += cv.w;
        }
        sx = fmaxf(sx, 0.f); sy = fmaxf(sy, 0.f);
        sz = fmaxf(sz, 0.f); sw_ = fmaxf(sw_, 0.f);
        *(float4*)&g_cams[((size_t)n * NO + o) * HW + hw] = make_float4(sx, sy, sz, sw_);
        lmax = fmaxf(fmaxf(sx, sy), fmaxf(sz, sw_));
    }

    __shared__ float smax[256];
    smax[tid] = lmax;
    __syncthreads();
#pragma unroll
    for (int s = 128; s > 0; s >>= 1) {
        if (tid < s) smax[tid] = fmaxf(smax[tid], smax[tid + s]);
        __syncthreads();
    }
    if (tid == 0) g_max[no] = smax[0];
}

// ---------------------------------------------------------------------------
// Kernel 2b: threshold + mean-drop map for one quarter. NBQ blocks, tiny.
// ---------------------------------------------------------------------------
__global__ __launch_bounds__(224) void k2b_mean(const float* __restrict__ gama_p,
                                                int n_base) {
    const int n   = n_base + blockIdx.x;
    const int tid = threadIdx.x;
    if (tid >= HW4) return;

    const float gama = *gama_p;
    const float thr0 = g_max[n * NO + 0] * gama;
    const float thr1 = g_max[n * NO + 1] * gama;
    const float thr2 = g_max[n * NO + 2] * gama;
    const float thr3 = g_max[n * NO + 3] * gama;

    const int hw = tid * 4;
    float4 c0 = *(const float4*)&g_cams[((size_t)n * NO + 0) * HW + hw];
    float4 c1 = *(const float4*)&g_cams[((size_t)n * NO + 1) * HW + hw];
    float4 c2 = *(const float4*)&g_cams[((size_t)n * NO + 2) * HW + hw];
    float4 c3 = *(const float4*)&g_cams[((size_t)n * NO + 3) * HW + hw];

    float4 m;
    m.x = ((c0.x > thr0 ? 0.f : c0.x) + (c1.x > thr1 ? 0.f : c1.x) +
           (c2.x > thr2 ? 0.f : c2.x) + (c3.x > thr3 ? 0.f : c3.x)) * 0.25f;
    m.y = ((c0.y > thr0 ? 0.f : c0.y) + (c1.y > thr1 ? 0.f : c1.y) +
           (c2.y > thr2 ? 0.f : c2.y) + (c3.y > thr3 ? 0.f : c3.y)) * 0.25f;
    m.z = ((c0.z > thr0 ? 0.f : c0.z) + (c1.z > thr1 ? 0.f : c1.z) +
           (c2.z > thr2 ? 0.f : c2.z) + (c3.z > thr3 ? 0.f : c3.z)) * 0.25f;
    m.w = ((c0.w > thr0 ? 0.f : c0.w) + (c1.w > thr1 ? 0.f : c1.w) +
           (c2.w > thr2 ? 0.f : c2.w) + (c3.w > thr3 ? 0.f : c3.w)) * 0.25f;
    *(float4*)&g_mean[(size_t)n * HW + hw] = m;
}

// ---------------------------------------------------------------------------
// Kernel 3: out = x * mean[n, hw] for one batch quarter. Flat float4/thread.
// x via __ldcs, out via __stcs. Block size 512 (half the blocks; coarser
// scheduling granularity, identical per-warp coalescing).
// ---------------------------------------------------------------------------
#define QTR4 ((unsigned int)NBQ * C * HW4)   // 6,422,528 float4 per quarter
__global__ __launch_bounds__(512) void k3_mul(const float* __restrict__ x,
                                              float* __restrict__ out,
                                              unsigned int i4_base) {
    unsigned int idx = blockIdx.x * blockDim.x + threadIdx.x;
    if (idx >= QTR4) return;
    unsigned int i4 = i4_base + idx;

    unsigned int hw4 = i4 % HW4;
    unsigned int nc  = i4 / HW4;
    unsigned int n   = nc / C;

    float4 xv = __ldcs((const float4*)x + i4);
    float4 m  = *(const float4*)&g_mean[(size_t)n * HW + hw4 * 4];
    float4 r;
    r.x = xv.x * m.x;
    r.y = xv.y * m.y;
    r.z = xv.z * m.z;
    r.w = xv.w * m.w;
    __stcs((float4*)out + i4, r);
}

// ---------------------------------------------------------------------------
// Symmetric 4-way fork-join (graph-capturable event fork/join on stream 0).
// Branch q handles n in [q*8, q*8+8). No cross-branch ordering: the four
// chains de-phase naturally, so each branch's reduction bubble overlaps the
// others' BW-bound kernels.
// ---------------------------------------------------------------------------
extern "C" void kernel_launch(void* const* d_in, const int* in_sizes, int n_in,
                              void* d_out, int out_size) {
    const float* x    = (const float*)d_in[0];
    const float* w    = (const float*)d_in[1];
    const float* gama = (const float*)d_in[2];
    float* out        = (float*)d_out;

    // Lazy one-time creation (correctness run precedes graph capture).
    static cudaStream_t ss[NBRANCH - 1] = {nullptr, nullptr, nullptr};
    static cudaEvent_t ev_fork = nullptr;
    static cudaEvent_t ev_join[NBRANCH - 1] = {nullptr, nullptr, nullptr};
    if (!ss[0]) {
        for (int i = 0; i < NBRANCH - 1; i++) {
            cudaStreamCreateWithFlags(&ss[i], cudaStreamNonBlocking);
            cudaEventCreateWithFlags(&ev_join[i], cudaEventDisableTiming);
        }
        cudaEventCreateWithFlags(&ev_fork, cudaEventDisableTiming);
    }

    // Fork
    cudaEventRecord(ev_fork, 0);
    for (int i = 0; i < NBRANCH - 1; i++)
        cudaStreamWaitEvent(ss[i], ev_fork, 0);

    dim3 g1(CHUNKS, NBQ);
    const unsigned int k3_blocks = (QTR4 + 511) / 512;

    for (int q = 0; q < NBRANCH; q++) {
        cudaStream_t st = (q == 0) ? (cudaStream_t)0 : ss[q - 1];
        const int nb = q * NBQ;
        k1_dot<<<g1, 256, 0, st>>>(x, w, nb);
        k2a_reduce<<<NBQ * NO, 256, 0, st>>>(nb);
        k2b_mean<<<NBQ, 224, 0, st>>>(gama, nb);
        k3_mul<<<k3_blocks, 512, 0, st>>>(x, out, (unsigned int)nb * C * HW4);
    }

    // Join
    for (int i = 0; i < NBRANCH - 1; i++) {
        cudaEventRecord(ev_join[i], ss[i]);
        cudaStreamWaitEvent(0, ev_join[i], 0);
    }
}

// round 17
// speedup vs baseline: 1.0352x; 1.0352x over previous
#include <cuda_runtime.h>

// Problem constants
#define NB    32
#define NBQ   8         // per-branch batch quarter
#define NBRANCH 4
#define C     4096
#define HW    784       // 28*28
#define HW4   196       // HW / 4 (float4 granularity)
#define NO    4         // output channels
#define CHUNKS 37       // 37*32 = 1184 k1 blocks total = 2 * (148 SMs * 4/SM)
#define CCMAX 111       // ceil(4096/37)

// Scratch (no allocation allowed)
__device__ float g_part[CHUNKS * NB * NO * HW];  // 14.86 MB partials (L2)
__device__ float g_cams[NB * NO * HW];           // 401 KB relu'd cams
__device__ float g_max[NB * NO];                 // per-(n,o) spatial max
__device__ float g_mean[NB * HW];                // 100 KB mean map

// ---------------------------------------------------------------------------
// Kernel 1: partial dot products for one batch quarter. grid=(CHUNKS, NBQ).
// x read with __ldcs (streaming); weights transposed in smem; unroll 8.
// ---------------------------------------------------------------------------
__global__ __launch_bounds__(256, 4) void k1_dot(const float* __restrict__ x,
                                                 const float* __restrict__ w,
                                                 int n_base) {
    const int cchunk = blockIdx.x;
    const int n      = n_base + blockIdx.y;
    const int tid    = threadIdx.x;

    const int cbeg = (cchunk * C) / CHUNKS;
    const int cend = ((cchunk + 1) * C) / CHUNKS;
    const int cc   = cend - cbeg;          // 110 or 111

    __shared__ float4 sw[CCMAX];           // transposed: sw[c] = {w0,w1,w2,w3}
    if (tid < cc) {
        int c = cbeg + tid;
        sw[tid] = make_float4(w[0 * C + c], w[1 * C + c],
                              w[2 * C + c], w[3 * C + c]);
    }
    __syncthreads();

    if (tid >= HW4) return;

    float a00 = 0.f, a01 = 0.f, a02 = 0.f, a03 = 0.f;
    float a10 = 0.f, a11 = 0.f, a12 = 0.f, a13 = 0.f;
    float a20 = 0.f, a21 = 0.f, a22 = 0.f, a23 = 0.f;
    float a30 = 0.f, a31 = 0.f, a32 = 0.f, a33 = 0.f;

    const float4* xb = (const float4*)(x + ((size_t)n * C + (size_t)cbeg) * HW) + tid;

#pragma unroll 8
    for (int c = 0; c < cc; c++) {
        float4 xv = __ldcs(xb + (size_t)c * HW4);
        float4 wv = sw[c];
        a00 += wv.x * xv.x; a01 += wv.x * xv.y; a02 += wv.x * xv.z; a03 += wv.x * xv.w;
        a10 += wv.y * xv.x; a11 += wv.y * xv.y; a12 += wv.y * xv.z; a13 += wv.y * xv.w;
        a20 += wv.z * xv.x; a21 += wv.z * xv.y; a22 += wv.z * xv.z; a23 += wv.z * xv.w;
        a30 += wv.w * xv.x; a31 += wv.w * xv.y; a32 += wv.w * xv.z; a33 += wv.w * xv.w;
    }

    const int hw = tid * 4;
    float* base = &g_part[(((size_t)cchunk * NB + n) * NO) * HW];
    *(float4*)(base + 0 * HW + hw) = make_float4(a00, a01, a02, a03);
    *(float4*)(base + 1 * HW + hw) = make_float4(a10, a11, a12, a13);
    *(float4*)(base + 2 * HW + hw) = make_float4(a20, a21, a22, a23);
    *(float4*)(base + 3 * HW + hw) = make_float4(a30, a31, a32, a33);
}

// ---------------------------------------------------------------------------
// Kernel 2a: chunk reduction + relu + per-(n,o) max for one quarter.
// grid = NBQ*NO = 32 blocks, 256 threads (power-of-2 tree).
// ---------------------------------------------------------------------------
__global__ __launch_bounds__(256) void k2a_reduce(int n_base) {
    const int no  = n_base * NO + blockIdx.x;
    const int n   = no >> 2;
    const int o   = no & 3;
    const int tid = threadIdx.x;

    float lmax = 0.f;                    // relu outputs >= 0
    if (tid < HW4) {
        const int hw = tid * 4;
        float sx = 0.f, sy = 0.f, sz = 0.f, sw_ = 0.f;
#pragma unroll
        for (int ch = 0; ch < CHUNKS; ch++) {
            const float* p = &g_part[(((size_t)ch * NB + n) * NO + o) * HW + hw];
            float4 cv = *(const float4*)p;
            sx += cv.x; sy += cv.y; sz += cv.z; sw_ += cv.w;
        }
        sx = fmaxf(sx, 0.f); sy = fmaxf(sy, 0.f);
        sz = fmaxf(sz, 0.f); sw_ = fmaxf(sw_, 0.f);
        *(float4*)&g_cams[((size_t)n * NO + o) * HW + hw] = make_float4(sx, sy, sz, sw_);
        lmax = fmaxf(fmaxf(sx, sy), fmaxf(sz, sw_));
    }

    __shared__ float smax[256];
    smax[tid] = lmax;
    __syncthreads();
#pragma unroll
    for (int s = 128; s > 0; s >>= 1) {
        if (tid < s) smax[tid] = fmaxf(smax[tid], smax[tid + s]);
        __syncthreads();
    }
    if (tid == 0) g_max[no] = smax[0];
}

// ---------------------------------------------------------------------------
// Kernel 2b: threshold + mean-drop map for one quarter. NBQ blocks, tiny.
// ---------------------------------------------------------------------------
__global__ __launch_bounds__(224) void k2b_mean(const float* __restrict__ gama_p,
                                                int n_base) {
    const int n   = n_base + blockIdx.x;
    const int tid = threadIdx.x;
    if (tid >= HW4) return;

    const float gama = *gama_p;
    const float thr0 = g_max[n * NO + 0] * gama;
    const float thr1 = g_max[n * NO + 1] * gama;
    const float thr2 = g_max[n * NO + 2] * gama;
    const float thr3 = g_max[n * NO + 3] * gama;

    const int hw = tid * 4;
    float4 c0 = *(const float4*)&g_cams[((size_t)n * NO + 0) * HW + hw];
    float4 c1 = *(const float4*)&g_cams[((size_t)n * NO + 1) * HW + hw];
    float4 c2 = *(const float4*)&g_cams[((size_t)n * NO + 2) * HW + hw];
    float4 c3 = *(const float4*)&g_cams[((size_t)n * NO + 3) * HW + hw];

    float4 m;
    m.x = ((c0.x > thr0 ? 0.f : c0.x) + (c1.x > thr1 ? 0.f : c1.x) +
           (c2.x > thr2 ? 0.f : c2.x) + (c3.x > thr3 ? 0.f : c3.x)) * 0.25f;
    m.y = ((c0.y > thr0 ? 0.f : c0.y) + (c1.y > thr1 ? 0.f : c1.y) +
           (c2.y > thr2 ? 0.f : c2.y) + (c3.y > thr3 ? 0.f : c3.y)) * 0.25f;
    m.z = ((c0.z > thr0 ? 0.f : c0.z) + (c1.z > thr1 ? 0.f : c1.z) +
           (c2.z > thr2 ? 0.f : c2.z) + (c3.z > thr3 ? 0.f : c3.z)) * 0.25f;
    m.w = ((c0.w > thr0 ? 0.f : c0.w) + (c1.w > thr1 ? 0.f : c1.w) +
           (c2.w > thr2 ? 0.f : c2.w) + (c3.w > thr3 ? 0.f : c3.w)) * 0.25f;
    *(float4*)&g_mean[(size_t)n * HW + hw] = m;
}

// ---------------------------------------------------------------------------
// Kernel 3: out = x * mean[n, hw] for one batch quarter. Flat float4/thread,
// 256-thread blocks. x via __ldcs, out via __stcs (proven-best form).
// ---------------------------------------------------------------------------
#define QTR4 ((unsigned int)NBQ * C * HW4)   // 6,422,528 float4 per quarter
__global__ __launch_bounds__(256) void k3_mul(const float* __restrict__ x,
                                              float* __restrict__ out,
                                              unsigned int i4_base) {
    unsigned int idx = blockIdx.x * blockDim.x + threadIdx.x;
    if (idx >= QTR4) return;
    unsigned int i4 = i4_base + idx;

    unsigned int hw4 = i4 % HW4;
    unsigned int nc  = i4 / HW4;
    unsigned int n   = nc / C;

    float4 xv = __ldcs((const float4*)x + i4);
    float4 m  = *(const float4*)&g_mean[(size_t)n * HW + hw4 * 4];
    float4 r;
    r.x = xv.x * m.x;
    r.y = xv.y * m.y;
    r.z = xv.z * m.z;
    r.w = xv.w * m.w;
    __stcs((float4*)out + i4, r);
}

// ---------------------------------------------------------------------------
// Symmetric 4-way fork-join (graph-capturable event fork/join on stream 0).
// Branch q handles n in [q*8, q*8+8). No cross-branch ordering: the four
// chains de-phase naturally, so each branch's reduction bubble overlaps the
// others' BW-bound kernels. (Champion: 197.8 us, reproduced 3x.)
// ---------------------------------------------------------------------------
extern "C" void kernel_launch(void* const* d_in, const int* in_sizes, int n_in,
                              void* d_out, int out_size) {
    const float* x    = (const float*)d_in[0];
    const float* w    = (const float*)d_in[1];
    const float* gama = (const float*)d_in[2];
    float* out        = (float*)d_out;

    // Lazy one-time creation (correctness run precedes graph capture).
    static cudaStream_t ss[NBRANCH - 1] = {nullptr, nullptr, nullptr};
    static cudaEvent_t ev_fork = nullptr;
    static cudaEvent_t ev_join[NBRANCH - 1] = {nullptr, nullptr, nullptr};
    if (!ss[0]) {
        for (int i = 0; i < NBRANCH - 1; i++) {
            cudaStreamCreateWithFlags(&ss[i], cudaStreamNonBlocking);
            cudaEventCreateWithFlags(&ev_join[i], cudaEventDisableTiming);
        }
        cudaEventCreateWithFlags(&ev_fork, cudaEventDisableTiming);
    }

    // Fork
    cudaEventRecord(ev_fork, 0);
    for (int i = 0; i < NBRANCH - 1; i++)
        cudaStreamWaitEvent(ss[i], ev_fork, 0);

    dim3 g1(CHUNKS, NBQ);
    const unsigned int k3_blocks = (QTR4 + 255) / 256;

    for (int q = 0; q < NBRANCH; q++) {
        cudaStream_t st = (q == 0) ? (cudaStream_t)0 : ss[q - 1];
        const int nb = q * NBQ;
        k1_dot<<<g1, 256, 0, st>>>(x, w, nb);
        k2a_reduce<<<NBQ * NO, 256, 0, st>>>(nb);
        k2b_mean<<<NBQ, 224, 0, st>>>(gama, nb);
        k3_mul<<<k3_blocks, 256, 0, st>>>(x, out, (unsigned int)nb * C * HW4);
    }

    // Join
    for (int i = 0; i < NBRANCH - 1; i++) {
        cudaEventRecord(ev_join[i], ss[i]);
        cudaStreamWaitEvent(0, ev_join[i], 0);
    }
}